// round 1
// baseline (speedup 1.0000x reference)
#include <cuda_runtime.h>
#include <math.h>
#include <stdint.h>

// ---------------- scratch (device globals; no allocations allowed) ----------------
__device__ float g_c1[16221184];   // 4*16*124*2044 (eval max)
__device__ float g_c2[31334400];   // 4*32*120*2040
__device__ float g_c3[60461056];   // 4*64*116*2036
__device__ float g_pool[30171136]; // 4*3712*2032
__device__ float g_lin[520192];    // 4*2032*64
__device__ float g_gru_e[520192];  // (4,2032,64)
__device__ float g_gru_t[262144];  // (4,1024,64)
__device__ float g_scores[8323072];// 4*1024*2032
__device__ float g_tt[520192];     // (4,2032,64)

// ---------------- conv 5x5 VALID, NCHW, register-blocked ----------------
// block (16,8): each thread computes 4 consecutive w outputs for 8 output channels.
template<int CIN>
__global__ __launch_bounds__(128)
void conv5x5_kernel(const float* __restrict__ in, const float* __restrict__ wt,
                    const float* __restrict__ bias, float* __restrict__ out,
                    int Hin, int Win, int Hout, int Wout, int CO)
{
    __shared__ float s_in[12][68];
    __shared__ float s_w[8 * 25];

    const int tx = threadIdx.x;          // 0..15
    const int ty = threadIdx.y;          // 0..7
    const int tid = ty * 16 + tx;
    const int w0 = blockIdx.x * 64;
    const int h0 = blockIdx.y * 8;
    const int groups = CO >> 3;
    const int b   = blockIdx.z / groups;
    const int co0 = (blockIdx.z % groups) * 8;

    float acc[8][4];
    #pragma unroll
    for (int i = 0; i < 8; i++)
        #pragma unroll
        for (int o = 0; o < 4; o++) acc[i][o] = 0.f;

    #pragma unroll 1
    for (int ci = 0; ci < CIN; ci++) {
        __syncthreads();
        const float* ip = in + ((size_t)(b * CIN + ci) * Hin) * Win;
        for (int idx = tid; idx < 12 * 68; idx += 128) {
            int r = idx / 68, c = idx % 68;
            int gh = h0 + r, gw = w0 + c;
            s_in[r][c] = (gh < Hin && gw < Win) ? ip[(size_t)gh * Win + gw] : 0.f;
        }
        for (int idx = tid; idx < 200; idx += 128) {
            int i = idx / 25, k = idx % 25;
            s_w[idx] = wt[((size_t)(co0 + i) * CIN + ci) * 25 + k];
        }
        __syncthreads();

        float p[5][8];
        #pragma unroll
        for (int r = 0; r < 5; r++)
            #pragma unroll
            for (int c = 0; c < 8; c++) p[r][c] = s_in[ty + r][tx * 4 + c];

        #pragma unroll
        for (int kh = 0; kh < 5; kh++) {
            #pragma unroll
            for (int kw = 0; kw < 5; kw++) {
                float wv[8];
                #pragma unroll
                for (int i = 0; i < 8; i++) wv[i] = s_w[i * 25 + kh * 5 + kw];
                #pragma unroll
                for (int o = 0; o < 4; o++) {
                    float v = p[kh][kw + o];
                    #pragma unroll
                    for (int i = 0; i < 8; i++) acc[i][o] = fmaf(v, wv[i], acc[i][o]);
                }
            }
        }
    }

    const int oh = h0 + ty;
    if (oh < Hout) {
        #pragma unroll
        for (int i = 0; i < 8; i++) {
            float bv = bias[co0 + i];
            float* op = out + ((size_t)(b * CO + co0 + i) * Hout + oh) * Wout;
            #pragma unroll
            for (int o = 0; o < 4; o++) {
                int ow = w0 + tx * 4 + o;
                if (ow < Wout) op[ow] = acc[i][o] + bv;
            }
        }
    }
}

// ---------------- maxpool window (2,5), stride (2,1) ----------------
__global__ __launch_bounds__(256)
void maxpool_kernel(const float* __restrict__ in, float* __restrict__ out,
                    int Wc, int Wp, int total)
{
    int idx = blockIdx.x * 256 + threadIdx.x;
    if (idx >= total) return;
    int w = idx % Wp;
    int t = idx / Wp;
    int h = t % 58;
    int bc = t / 58;
    const float* ip = in + ((size_t)bc * 116 + 2 * h) * Wc + w;
    float m = -1e30f;
    #pragma unroll
    for (int r = 0; r < 2; r++)
        #pragma unroll
        for (int c = 0; c < 5; c++) m = fmaxf(m, ip[(size_t)r * Wc + c]);
    out[idx] = m;
}

// ---------------- GEMM: C[M,64] = A[M,K] @ W[64,K]^T + bias ----------------
__global__ __launch_bounds__(256)
void gemm_nt64_kernel(const float* __restrict__ A, const float* __restrict__ W,
                      const float* __restrict__ bias, float* __restrict__ C,
                      int M, int K)
{
    __shared__ __align__(16) float As[16][64];
    __shared__ __align__(16) float Bs[16][64];
    const int tid = threadIdx.x;
    const int m0 = blockIdx.x * 64;
    const int tm = tid >> 4, tn = tid & 15;
    const int lm = tid >> 2, lj = (tid & 3) * 4;

    float acc[4][4];
    #pragma unroll
    for (int i = 0; i < 4; i++)
        #pragma unroll
        for (int j = 0; j < 4; j++) acc[i][j] = 0.f;

    for (int k0 = 0; k0 < K; k0 += 16) {
        float4 av = *(const float4*)&A[(size_t)(m0 + lm) * K + k0 + lj];
        float4 wv = *(const float4*)&W[(size_t)lm * K + k0 + lj];
        __syncthreads();
        As[lj + 0][lm] = av.x; As[lj + 1][lm] = av.y; As[lj + 2][lm] = av.z; As[lj + 3][lm] = av.w;
        Bs[lj + 0][lm] = wv.x; Bs[lj + 1][lm] = wv.y; Bs[lj + 2][lm] = wv.z; Bs[lj + 3][lm] = wv.w;
        __syncthreads();
        #pragma unroll
        for (int kk = 0; kk < 16; kk++) {
            float4 a  = *(const float4*)&As[kk][tm * 4];
            float4 bb = *(const float4*)&Bs[kk][tn * 4];
            float ar[4] = {a.x, a.y, a.z, a.w};
            float br[4] = {bb.x, bb.y, bb.z, bb.w};
            #pragma unroll
            for (int i = 0; i < 4; i++)
                #pragma unroll
                for (int j = 0; j < 4; j++) acc[i][j] = fmaf(ar[i], br[j], acc[i][j]);
        }
    }
    #pragma unroll
    for (int i = 0; i < 4; i++)
        #pragma unroll
        for (int j = 0; j < 4; j++)
            C[(size_t)(m0 + tm * 4 + i) * 64 + tn * 4 + j] = acc[i][j] + bias[tn * 4 + j];
}

// ---------------- GRU (parallel over rows; 4 sequential steps over batch) ----------------
__global__ __launch_bounds__(256)
void gru_kernel(const float* __restrict__ lin, const float* __restrict__ wih,
                const float* __restrict__ whh, const float* __restrict__ bih,
                const float* __restrict__ bhh, float* __restrict__ out, int T)
{
    const int d = threadIdx.x;           // 0..63
    const int ty = threadIdx.y;          // 0..3
    const int row = blockIdx.x * 4 + ty;
    __shared__ float s_x[4][64];
    __shared__ float s_h[4][64];
    s_h[ty][d] = 0.f;

    const float bir = bih[d], biz = bih[64 + d], bin_ = bih[128 + d];
    const float bhr = bhh[d], bhz = bhh[64 + d], bhn  = bhh[128 + d];

    for (int s = 0; s < 4; s++) {
        __syncthreads();
        s_x[ty][d] = lin[((size_t)s * T + row) * 64 + d];
        __syncthreads();
        float gir = bir, giz = biz, gin = bin_;
        float ghr = bhr, ghz = bhz, ghn = bhn;
        #pragma unroll 8
        for (int k = 0; k < 64; k++) {
            float xv = s_x[ty][k], hv = s_h[ty][k];
            gir = fmaf(xv, wih[d * 64 + k], gir);
            giz = fmaf(xv, wih[(64 + d) * 64 + k], giz);
            gin = fmaf(xv, wih[(128 + d) * 64 + k], gin);
            ghr = fmaf(hv, whh[d * 64 + k], ghr);
            ghz = fmaf(hv, whh[(64 + d) * 64 + k], ghz);
            ghn = fmaf(hv, whh[(128 + d) * 64 + k], ghn);
        }
        float r = 1.f / (1.f + expf(-(gir + ghr)));
        float z = 1.f / (1.f + expf(-(giz + ghz)));
        float n = tanhf(gin + r * ghn);
        float hprev = s_h[ty][d];
        float hn = (1.f - z) * n + z * hprev;
        __syncthreads();
        s_h[ty][d] = hn;
        out[((size_t)s * T + row) * 64 + d] = hn;
    }
}

// ---------------- scores + softmax over e: P[b,t,e] ----------------
__global__ __launch_bounds__(256)
void scores_softmax_kernel(const float* __restrict__ tf, const float* __restrict__ ef,
                           float* __restrict__ P, int Tt, int Te)
{
    const int b = blockIdx.y, t = blockIdx.x, tid = threadIdx.x;
    __shared__ float s_t[64];
    __shared__ float s_red[256];
    if (tid < 64) s_t[tid] = tf[((size_t)b * Tt + t) * 64 + tid];
    __syncthreads();

    float sc[8];
    float lmax = -1e30f;
    #pragma unroll
    for (int ei = 0; ei < 8; ei++) {
        int e = ei * 256 + tid;
        float v = -1e30f;
        if (e < Te) {
            const float4* ep = (const float4*)&ef[((size_t)b * Te + e) * 64];
            float a = 0.f;
            #pragma unroll
            for (int q = 0; q < 16; q++) {
                float4 x = ep[q];
                a = fmaf(x.x, s_t[4 * q + 0], a);
                a = fmaf(x.y, s_t[4 * q + 1], a);
                a = fmaf(x.z, s_t[4 * q + 2], a);
                a = fmaf(x.w, s_t[4 * q + 3], a);
            }
            v = a;
        }
        sc[ei] = v;
        lmax = fmaxf(lmax, v);
    }
    s_red[tid] = lmax; __syncthreads();
    for (int s = 128; s > 0; s >>= 1) { if (tid < s) s_red[tid] = fmaxf(s_red[tid], s_red[tid + s]); __syncthreads(); }
    float m = s_red[0]; __syncthreads();

    float lsum = 0.f;
    #pragma unroll
    for (int ei = 0; ei < 8; ei++) {
        int e = ei * 256 + tid;
        if (e < Te) { sc[ei] = expf(sc[ei] - m); lsum += sc[ei]; }
    }
    s_red[tid] = lsum; __syncthreads();
    for (int s = 128; s > 0; s >>= 1) { if (tid < s) s_red[tid] += s_red[tid + s]; __syncthreads(); }
    float inv = 1.f / s_red[0];

    float* Pr = P + ((size_t)b * Tt + t) * Te;
    #pragma unroll
    for (int ei = 0; ei < 8; ei++) {
        int e = ei * 256 + tid;
        if (e < Te) Pr[e] = sc[ei] * inv;
    }
}

// ---------------- tt[b,e,d] = |sum_t P[b,t,e]*TF[b,t,d] - EF[b,e,d]| ----------------
__global__ __launch_bounds__(256)
void gemm_tt_kernel(const float* __restrict__ P, const float* __restrict__ TF,
                    const float* __restrict__ EF, float* __restrict__ OUT,
                    int Tt, int Te)
{
    __shared__ __align__(16) float As[16][64];   // [k=t][m=e]
    __shared__ __align__(16) float Bs[16][64];   // [k=t][n=d]
    const int tid = threadIdx.x;
    const int b = blockIdx.y;
    const int e0 = blockIdx.x * 64;
    const int tm = tid >> 4, tn = tid & 15;
    const int kt = tid >> 4, c4 = (tid & 15) * 4;

    float acc[4][4];
    #pragma unroll
    for (int i = 0; i < 4; i++)
        #pragma unroll
        for (int j = 0; j < 4; j++) acc[i][j] = 0.f;

    for (int t0 = 0; t0 < Tt; t0 += 16) {
        float4 av = make_float4(0.f, 0.f, 0.f, 0.f);
        if (e0 + c4 < Te)
            av = *(const float4*)&P[((size_t)b * Tt + t0 + kt) * Te + e0 + c4];
        float4 bv = *(const float4*)&TF[((size_t)b * Tt + t0 + kt) * 64 + c4];
        __syncthreads();
        *(float4*)&As[kt][c4] = av;
        *(float4*)&Bs[kt][c4] = bv;
        __syncthreads();
        #pragma unroll
        for (int kk = 0; kk < 16; kk++) {
            float4 a  = *(const float4*)&As[kk][tm * 4];
            float4 bb = *(const float4*)&Bs[kk][tn * 4];
            float ar[4] = {a.x, a.y, a.z, a.w};
            float br[4] = {bb.x, bb.y, bb.z, bb.w};
            #pragma unroll
            for (int i = 0; i < 4; i++)
                #pragma unroll
                for (int j = 0; j < 4; j++) acc[i][j] = fmaf(ar[i], br[j], acc[i][j]);
        }
    }
    #pragma unroll
    for (int i = 0; i < 4; i++) {
        int e = e0 + tm * 4 + i;
        if (e < Te) {
            #pragma unroll
            for (int j = 0; j < 4; j++) {
                int d = tn * 4 + j;
                size_t off = ((size_t)b * Te + e) * 64 + d;
                OUT[off] = fabsf(acc[i][j] - EF[off]);
            }
        }
    }
}

// ---------------- final: attention pooling + MLP head + softmax ----------------
__global__ __launch_bounds__(256)
void final_kernel(const float* __restrict__ tt, const float* __restrict__ ef,
                  const float* __restrict__ aw, const float* __restrict__ ab,
                  const float* __restrict__ hw, const float* __restrict__ hb,
                  const float* __restrict__ cw, const float* __restrict__ cb,
                  float* __restrict__ out, int Te)
{
    const int b = blockIdx.x, tid = threadIdx.x;
    __shared__ float s_prob[2048];
    __shared__ float s_tmp[256];
    __shared__ float s_red[64];
    __shared__ float s_h[128];

    float loc[8];
    float lmax = -1e30f;
    #pragma unroll
    for (int ei = 0; ei < 8; ei++) {
        int e = ei * 256 + tid;
        float v = -1e30f;
        if (e < Te) {
            const float4* ep = (const float4*)&ef[((size_t)b * Te + e) * 64];
            float a = 0.f;
            #pragma unroll
            for (int q = 0; q < 16; q++) {
                float4 x = ep[q];
                a = fmaf(x.x, aw[4 * q + 0], a);
                a = fmaf(x.y, aw[4 * q + 1], a);
                a = fmaf(x.z, aw[4 * q + 2], a);
                a = fmaf(x.w, aw[4 * q + 3], a);
            }
            v = a + ab[0];
        }
        loc[ei] = v; lmax = fmaxf(lmax, v);
    }
    s_tmp[tid] = lmax; __syncthreads();
    for (int s = 128; s > 0; s >>= 1) { if (tid < s) s_tmp[tid] = fmaxf(s_tmp[tid], s_tmp[tid + s]); __syncthreads(); }
    float m = s_tmp[0]; __syncthreads();

    float lsum = 0.f;
    #pragma unroll
    for (int ei = 0; ei < 8; ei++) {
        int e = ei * 256 + tid;
        if (e < Te) { float ex = expf(loc[ei] - m); s_prob[e] = ex; lsum += ex; }
    }
    s_tmp[tid] = lsum; __syncthreads();
    for (int s = 128; s > 0; s >>= 1) { if (tid < s) s_tmp[tid] += s_tmp[tid + s]; __syncthreads(); }
    float inv = 1.f / s_tmp[0];
    __syncthreads();

    // red[d] = sum_e tt[b,e,d]*prob[e]
    const int d = tid & 63, part = tid >> 6;
    float acc = 0.f;
    for (int e = part; e < Te; e += 4)
        acc = fmaf(tt[((size_t)b * Te + e) * 64 + d], s_prob[e], acc);
    s_tmp[tid] = acc; __syncthreads();
    if (tid < 64)
        s_red[tid] = (s_tmp[tid] + s_tmp[tid + 64] + s_tmp[tid + 128] + s_tmp[tid + 192]) * inv;
    __syncthreads();

    if (tid < 128) {
        float a = hb[tid];
        #pragma unroll 8
        for (int k = 0; k < 64; k++) a = fmaf(s_red[k], hw[tid * 64 + k], a);
        s_h[tid] = fmaxf(a, 0.f);
    }
    __syncthreads();

    if (tid == 0) {
        float l0 = cb[0], l1 = cb[1];
        for (int j = 0; j < 128; j++) {
            l0 = fmaf(s_h[j], cw[j], l0);
            l1 = fmaf(s_h[j], cw[128 + j], l1);
        }
        float mm = fmaxf(l0, l1);
        float e0 = expf(l0 - mm), e1 = expf(l1 - mm);
        float s = e0 + e1;
        out[b * 2 + 0] = e0 / s;
        out[b * 2 + 1] = e1 / s;
    }
}

// ---------------- host driver ----------------
static void run_branch(const float* input, int Win0,
                       const float* w1, const float* b1,
                       const float* w2, const float* b2,
                       const float* w3, const float* b3,
                       const float* lw, const float* lb,
                       const float* wih, const float* whh,
                       const float* bih, const float* bhh,
                       float* gru_out,
                       float* pc1, float* pc2, float* pc3, float* ppool, float* plin)
{
    const int W1 = Win0 - 4, W2 = Win0 - 8, W3 = Win0 - 12, Wp = Win0 - 16;
    const int T = Wp;
    dim3 blk(16, 8);

    conv5x5_kernel<1><<<dim3((W1 + 63) / 64, (124 + 7) / 8, 4 * 2), blk>>>(
        input, w1, b1, pc1, 128, Win0, 124, W1, 16);
    conv5x5_kernel<16><<<dim3((W2 + 63) / 64, (120 + 7) / 8, 4 * 4), blk>>>(
        pc1, w2, b2, pc2, 124, W1, 120, W2, 32);
    conv5x5_kernel<32><<<dim3((W3 + 63) / 64, (116 + 7) / 8, 4 * 8), blk>>>(
        pc2, w3, b3, pc3, 120, W2, 116, W3, 64);

    int ptotal = 4 * 64 * 58 * Wp;
    maxpool_kernel<<<(ptotal + 255) / 256, 256>>>(pc3, ppool, W3, Wp, ptotal);

    gemm_nt64_kernel<<<(4 * T) / 64, 256>>>(ppool, lw, lb, plin, 4 * T, 3712);
    gru_kernel<<<T / 4, dim3(64, 4)>>>(plin, wih, whh, bih, bhh, gru_out, T);
}

extern "C" void kernel_launch(void* const* d_in, const int* in_sizes, int n_in,
                              void* d_out, int out_size)
{
    (void)in_sizes; (void)n_in; (void)out_size;

    const float* evaluation = (const float*)d_in[0];
    const float* templ      = (const float*)d_in[1];
    const float* e_w1 = (const float*)d_in[2];  const float* e_b1 = (const float*)d_in[3];
    const float* e_w2 = (const float*)d_in[4];  const float* e_b2 = (const float*)d_in[5];
    const float* e_w3 = (const float*)d_in[6];  const float* e_b3 = (const float*)d_in[7];
    const float* el_w = (const float*)d_in[8];  const float* el_b = (const float*)d_in[9];
    const float* eg_wih = (const float*)d_in[10]; const float* eg_whh = (const float*)d_in[11];
    const float* eg_bih = (const float*)d_in[12]; const float* eg_bhh = (const float*)d_in[13];
    const float* t_w1 = (const float*)d_in[14]; const float* t_b1 = (const float*)d_in[15];
    const float* t_w2 = (const float*)d_in[16]; const float* t_b2 = (const float*)d_in[17];
    const float* t_w3 = (const float*)d_in[18]; const float* t_b3 = (const float*)d_in[19];
    const float* tl_w = (const float*)d_in[20]; const float* tl_b = (const float*)d_in[21];
    const float* tg_wih = (const float*)d_in[22]; const float* tg_whh = (const float*)d_in[23];
    const float* tg_bih = (const float*)d_in[24]; const float* tg_bhh = (const float*)d_in[25];
    const float* a_w = (const float*)d_in[26]; const float* a_b = (const float*)d_in[27];
    const float* h_w = (const float*)d_in[28]; const float* h_b = (const float*)d_in[29];
    const float* c_w = (const float*)d_in[30]; const float* c_b = (const float*)d_in[31];

    float *pc1, *pc2, *pc3, *ppool, *plin, *pge, *pgt, *psc, *ptt;
    cudaGetSymbolAddress((void**)&pc1,  g_c1);
    cudaGetSymbolAddress((void**)&pc2,  g_c2);
    cudaGetSymbolAddress((void**)&pc3,  g_c3);
    cudaGetSymbolAddress((void**)&ppool, g_pool);
    cudaGetSymbolAddress((void**)&plin, g_lin);
    cudaGetSymbolAddress((void**)&pge,  g_gru_e);
    cudaGetSymbolAddress((void**)&pgt,  g_gru_t);
    cudaGetSymbolAddress((void**)&psc,  g_scores);
    cudaGetSymbolAddress((void**)&ptt,  g_tt);

    // Branches (sequential on default stream; buffers reused safely)
    run_branch(evaluation, 2048, e_w1, e_b1, e_w2, e_b2, e_w3, e_b3,
               el_w, el_b, eg_wih, eg_whh, eg_bih, eg_bhh, pge,
               pc1, pc2, pc3, ppool, plin);
    run_branch(templ, 1040, t_w1, t_b1, t_w2, t_b2, t_w3, t_b3,
               tl_w, tl_b, tg_wih, tg_whh, tg_bih, tg_bhh, pgt,
               pc1, pc2, pc3, ppool, plin);

    const int Tt = 1024, Te = 2032;
    scores_softmax_kernel<<<dim3(Tt, 4), 256>>>(pgt, pge, psc, Tt, Te);
    gemm_tt_kernel<<<dim3((Te + 63) / 64, 4), 256>>>(psc, pgt, pge, ptt, Tt, Te);
    final_kernel<<<4, 256>>>(ptt, pge, a_w, a_b, h_w, h_b, c_w, c_b,
                             (float*)d_out, Te);
}

// round 2
// speedup vs baseline: 1.1070x; 1.1070x over previous
#include <cuda_runtime.h>
#include <math.h>
#include <stdint.h>

// ---------------- scratch (device globals; no allocations allowed) ----------------
__device__ float g_c1[16221184];   // 4*16*124*2044 (eval max)
__device__ float g_c2[31334400];   // 4*32*120*2040
__device__ float g_c3[60461056];   // 4*64*116*2036
__device__ float g_pool[30171136]; // 4*3712*2032
__device__ float g_lin[520192];    // 4*2032*64
__device__ float g_gru_e[520192];  // (4,2032,64)
__device__ float g_gru_t[262144];  // (4,1024,64)
__device__ float g_scores[8323072];// 4*1024*2032
__device__ float g_tt[520192];     // (4,2032,64)

// ---------------- packed f32x2 helpers (Blackwell FFMA2) ----------------
__device__ __forceinline__ unsigned long long pack2(float lo, float hi) {
    unsigned long long r;
    asm("mov.b64 %0, {%1, %2};" : "=l"(r) : "f"(lo), "f"(hi));
    return r;
}
__device__ __forceinline__ void unpack2(unsigned long long v, float& lo, float& hi) {
    asm("mov.b64 {%0, %1}, %2;" : "=f"(lo), "=f"(hi) : "l"(v));
}
__device__ __forceinline__ unsigned long long fma2(unsigned long long a,
                                                   unsigned long long b,
                                                   unsigned long long c) {
    unsigned long long d;
    asm("fma.rn.f32x2 %0, %1, %2, %3;" : "=l"(d) : "l"(a), "l"(b), "l"(c));
    return d;
}

// ---------------- conv 5x5 VALID, NCHW, register-blocked, f32x2 FMA ----------------
// block (16,8): each thread computes 4 consecutive w outputs (2 packed pairs)
// for 8 output channels.
template<int CIN>
__global__ __launch_bounds__(128)
void conv5x5_kernel(const float* __restrict__ in, const float* __restrict__ wt,
                    const float* __restrict__ bias, float* __restrict__ out,
                    int Hin, int Win, int Hout, int Wout, int CO)
{
    __shared__ __align__(16) float s_in[12][68];
    __shared__ unsigned long long s_w2[200];   // weights dup-packed (w,w)

    const int tx = threadIdx.x;          // 0..15
    const int ty = threadIdx.y;          // 0..7
    const int tid = ty * 16 + tx;
    const int w0 = blockIdx.x * 64;
    const int h0 = blockIdx.y * 8;
    const int groups = CO >> 3;
    const int b   = blockIdx.z / groups;
    const int co0 = (blockIdx.z % groups) * 8;

    unsigned long long acc2[8][2];
    #pragma unroll
    for (int i = 0; i < 8; i++) { acc2[i][0] = 0ull; acc2[i][1] = 0ull; }

    #pragma unroll 1
    for (int ci = 0; ci < CIN; ci++) {
        __syncthreads();
        const float* ip = in + ((size_t)(b * CIN + ci) * Hin) * Win;
        // tile fill: 12 rows x 17 float4 (= 68 floats); all Win are %4==0
        for (int idx = tid; idx < 204; idx += 128) {
            int r = idx / 17, j = idx % 17;
            int gh = h0 + r, gw = w0 + 4 * j;
            float4 v = make_float4(0.f, 0.f, 0.f, 0.f);
            if (gh < Hin && gw < Win) v = *(const float4*)&ip[(size_t)gh * Win + gw];
            *(float4*)&s_in[r][4 * j] = v;
        }
        for (int idx = tid; idx < 200; idx += 128) {
            int i = idx / 25, k = idx % 25;
            float w = wt[((size_t)(co0 + i) * CIN + ci) * 25 + k];
            s_w2[idx] = pack2(w, w);
        }
        __syncthreads();

        #pragma unroll
        for (int kh = 0; kh < 5; kh++) {
            float p[8];
            #pragma unroll
            for (int c = 0; c < 8; c++) p[c] = s_in[ty + kh][tx * 4 + c];
            unsigned long long p2[7];
            #pragma unroll
            for (int c = 0; c < 7; c++) p2[c] = pack2(p[c], p[c + 1]);

            #pragma unroll
            for (int kw = 0; kw < 5; kw++) {
                #pragma unroll
                for (int i = 0; i < 8; i++) {
                    unsigned long long w2 = s_w2[i * 25 + kh * 5 + kw];
                    acc2[i][0] = fma2(p2[kw],     w2, acc2[i][0]);
                    acc2[i][1] = fma2(p2[kw + 2], w2, acc2[i][1]);
                }
            }
        }
    }

    const int oh = h0 + ty;
    const int ow = w0 + tx * 4;
    if (oh < Hout && ow < Wout) {       // Wout%4==0 and ow%4==0 -> full float4 ok
        #pragma unroll
        for (int i = 0; i < 8; i++) {
            float bv = bias[co0 + i];
            float a0, a1, a2, a3;
            unpack2(acc2[i][0], a0, a1);
            unpack2(acc2[i][1], a2, a3);
            float4 v = make_float4(a0 + bv, a1 + bv, a2 + bv, a3 + bv);
            *(float4*)&out[((size_t)(b * CO + co0 + i) * Hout + oh) * Wout + ow] = v;
        }
    }
}

// ---------------- maxpool window (2,5), stride (2,1) ----------------
__global__ __launch_bounds__(256)
void maxpool_kernel(const float* __restrict__ in, float* __restrict__ out,
                    int Wc, int Wp, int total)
{
    int idx = blockIdx.x * 256 + threadIdx.x;
    if (idx >= total) return;
    int w = idx % Wp;
    int t = idx / Wp;
    int h = t % 58;
    int bc = t / 58;
    const float* ip = in + ((size_t)bc * 116 + 2 * h) * Wc + w;
    float m = -1e30f;
    #pragma unroll
    for (int r = 0; r < 2; r++)
        #pragma unroll
        for (int c = 0; c < 5; c++) m = fmaxf(m, ip[(size_t)r * Wc + c]);
    out[idx] = m;
}

// ---------------- GEMM: C[M,64] = A[M,K] @ W[64,K]^T + bias (f32x2) ----------------
__global__ __launch_bounds__(256)
void gemm_nt64_kernel(const float* __restrict__ A, const float* __restrict__ W,
                      const float* __restrict__ bias, float* __restrict__ C,
                      int M, int K)
{
    __shared__ __align__(16) float As[16][64];
    __shared__ __align__(16) float Bs[16][64];
    const int tid = threadIdx.x;
    const int m0 = blockIdx.x * 64;
    const int tm = tid >> 4, tn = tid & 15;
    const int lm = tid >> 2, lj = (tid & 3) * 4;

    unsigned long long acc2[4][2];
    #pragma unroll
    for (int i = 0; i < 4; i++) { acc2[i][0] = 0ull; acc2[i][1] = 0ull; }

    for (int k0 = 0; k0 < K; k0 += 16) {
        float4 av = *(const float4*)&A[(size_t)(m0 + lm) * K + k0 + lj];
        float4 wv = *(const float4*)&W[(size_t)lm * K + k0 + lj];
        __syncthreads();
        As[lj + 0][lm] = av.x; As[lj + 1][lm] = av.y; As[lj + 2][lm] = av.z; As[lj + 3][lm] = av.w;
        Bs[lj + 0][lm] = wv.x; Bs[lj + 1][lm] = wv.y; Bs[lj + 2][lm] = wv.z; Bs[lj + 3][lm] = wv.w;
        __syncthreads();
        #pragma unroll
        for (int kk = 0; kk < 16; kk++) {
            const unsigned long long* ap = (const unsigned long long*)&As[kk][tm * 4];
            const unsigned long long* bp = (const unsigned long long*)&Bs[kk][tn * 4];
            unsigned long long b01 = bp[0], b23 = bp[1];
            float a0, a1, a2, a3;
            unpack2(ap[0], a0, a1);
            unpack2(ap[1], a2, a3);
            unsigned long long d0 = pack2(a0, a0), d1 = pack2(a1, a1);
            unsigned long long d2 = pack2(a2, a2), d3 = pack2(a3, a3);
            acc2[0][0] = fma2(d0, b01, acc2[0][0]); acc2[0][1] = fma2(d0, b23, acc2[0][1]);
            acc2[1][0] = fma2(d1, b01, acc2[1][0]); acc2[1][1] = fma2(d1, b23, acc2[1][1]);
            acc2[2][0] = fma2(d2, b01, acc2[2][0]); acc2[2][1] = fma2(d2, b23, acc2[2][1]);
            acc2[3][0] = fma2(d3, b01, acc2[3][0]); acc2[3][1] = fma2(d3, b23, acc2[3][1]);
        }
    }
    #pragma unroll
    for (int i = 0; i < 4; i++) {
        float c0, c1, c2, c3;
        unpack2(acc2[i][0], c0, c1);
        unpack2(acc2[i][1], c2, c3);
        float* cp = &C[(size_t)(m0 + tm * 4 + i) * 64 + tn * 4];
        cp[0] = c0 + bias[tn * 4 + 0];
        cp[1] = c1 + bias[tn * 4 + 1];
        cp[2] = c2 + bias[tn * 4 + 2];
        cp[3] = c3 + bias[tn * 4 + 3];
    }
}

// ---------------- GRU (parallel over rows; 4 sequential steps over batch) ----------------
__global__ __launch_bounds__(256)
void gru_kernel(const float* __restrict__ lin, const float* __restrict__ wih,
                const float* __restrict__ whh, const float* __restrict__ bih,
                const float* __restrict__ bhh, float* __restrict__ out, int T)
{
    const int d = threadIdx.x;           // 0..63
    const int ty = threadIdx.y;          // 0..3
    const int row = blockIdx.x * 4 + ty;
    __shared__ float s_x[4][64];
    __shared__ float s_h[4][64];
    s_h[ty][d] = 0.f;

    const float bir = bih[d], biz = bih[64 + d], bin_ = bih[128 + d];
    const float bhr = bhh[d], bhz = bhh[64 + d], bhn  = bhh[128 + d];

    for (int s = 0; s < 4; s++) {
        __syncthreads();
        s_x[ty][d] = lin[((size_t)s * T + row) * 64 + d];
        __syncthreads();
        float gir = bir, giz = biz, gin = bin_;
        float ghr = bhr, ghz = bhz, ghn = bhn;
        #pragma unroll 8
        for (int k = 0; k < 64; k++) {
            float xv = s_x[ty][k], hv = s_h[ty][k];
            gir = fmaf(xv, wih[d * 64 + k], gir);
            giz = fmaf(xv, wih[(64 + d) * 64 + k], giz);
            gin = fmaf(xv, wih[(128 + d) * 64 + k], gin);
            ghr = fmaf(hv, whh[d * 64 + k], ghr);
            ghz = fmaf(hv, whh[(64 + d) * 64 + k], ghz);
            ghn = fmaf(hv, whh[(128 + d) * 64 + k], ghn);
        }
        float r = 1.f / (1.f + expf(-(gir + ghr)));
        float z = 1.f / (1.f + expf(-(giz + ghz)));
        float n = tanhf(gin + r * ghn);
        float hprev = s_h[ty][d];
        float hn = (1.f - z) * n + z * hprev;
        __syncthreads();
        s_h[ty][d] = hn;
        out[((size_t)s * T + row) * 64 + d] = hn;
    }
}

// ---------------- scores + softmax over e: P[b,t,e] ----------------
__global__ __launch_bounds__(256)
void scores_softmax_kernel(const float* __restrict__ tf, const float* __restrict__ ef,
                           float* __restrict__ P, int Tt, int Te)
{
    const int b = blockIdx.y, t = blockIdx.x, tid = threadIdx.x;
    __shared__ float s_t[64];
    __shared__ float s_red[256];
    if (tid < 64) s_t[tid] = tf[((size_t)b * Tt + t) * 64 + tid];
    __syncthreads();

    float sc[8];
    float lmax = -1e30f;
    #pragma unroll
    for (int ei = 0; ei < 8; ei++) {
        int e = ei * 256 + tid;
        float v = -1e30f;
        if (e < Te) {
            const float4* ep = (const float4*)&ef[((size_t)b * Te + e) * 64];
            float a = 0.f;
            #pragma unroll
            for (int q = 0; q < 16; q++) {
                float4 x = ep[q];
                a = fmaf(x.x, s_t[4 * q + 0], a);
                a = fmaf(x.y, s_t[4 * q + 1], a);
                a = fmaf(x.z, s_t[4 * q + 2], a);
                a = fmaf(x.w, s_t[4 * q + 3], a);
            }
            v = a;
        }
        sc[ei] = v;
        lmax = fmaxf(lmax, v);
    }
    s_red[tid] = lmax; __syncthreads();
    for (int s = 128; s > 0; s >>= 1) { if (tid < s) s_red[tid] = fmaxf(s_red[tid], s_red[tid + s]); __syncthreads(); }
    float m = s_red[0]; __syncthreads();

    float lsum = 0.f;
    #pragma unroll
    for (int ei = 0; ei < 8; ei++) {
        int e = ei * 256 + tid;
        if (e < Te) { sc[ei] = expf(sc[ei] - m); lsum += sc[ei]; }
    }
    s_red[tid] = lsum; __syncthreads();
    for (int s = 128; s > 0; s >>= 1) { if (tid < s) s_red[tid] += s_red[tid + s]; __syncthreads(); }
    float inv = 1.f / s_red[0];

    float* Pr = P + ((size_t)b * Tt + t) * Te;
    #pragma unroll
    for (int ei = 0; ei < 8; ei++) {
        int e = ei * 256 + tid;
        if (e < Te) Pr[e] = sc[ei] * inv;
    }
}

// ---------------- tt[b,e,d] = |sum_t P[b,t,e]*TF[b,t,d] - EF[b,e,d]| (f32x2) ----------------
__global__ __launch_bounds__(256)
void gemm_tt_kernel(const float* __restrict__ P, const float* __restrict__ TF,
                    const float* __restrict__ EF, float* __restrict__ OUT,
                    int Tt, int Te)
{
    __shared__ __align__(16) float As[16][64];   // [k=t][m=e]
    __shared__ __align__(16) float Bs[16][64];   // [k=t][n=d]
    const int tid = threadIdx.x;
    const int b = blockIdx.y;
    const int e0 = blockIdx.x * 64;
    const int tm = tid >> 4, tn = tid & 15;
    const int kt = tid >> 4, c4 = (tid & 15) * 4;

    unsigned long long acc2[4][2];
    #pragma unroll
    for (int i = 0; i < 4; i++) { acc2[i][0] = 0ull; acc2[i][1] = 0ull; }

    for (int t0 = 0; t0 < Tt; t0 += 16) {
        float4 av = make_float4(0.f, 0.f, 0.f, 0.f);
        if (e0 + c4 < Te)
            av = *(const float4*)&P[((size_t)b * Tt + t0 + kt) * Te + e0 + c4];
        float4 bv = *(const float4*)&TF[((size_t)b * Tt + t0 + kt) * 64 + c4];
        __syncthreads();
        *(float4*)&As[kt][c4] = av;
        *(float4*)&Bs[kt][c4] = bv;
        __syncthreads();
        #pragma unroll
        for (int kk = 0; kk < 16; kk++) {
            const unsigned long long* ap = (const unsigned long long*)&As[kk][tm * 4];
            const unsigned long long* bp = (const unsigned long long*)&Bs[kk][tn * 4];
            unsigned long long b01 = bp[0], b23 = bp[1];
            float a0, a1, a2, a3;
            unpack2(ap[0], a0, a1);
            unpack2(ap[1], a2, a3);
            unsigned long long d0 = pack2(a0, a0), d1 = pack2(a1, a1);
            unsigned long long d2 = pack2(a2, a2), d3 = pack2(a3, a3);
            acc2[0][0] = fma2(d0, b01, acc2[0][0]); acc2[0][1] = fma2(d0, b23, acc2[0][1]);
            acc2[1][0] = fma2(d1, b01, acc2[1][0]); acc2[1][1] = fma2(d1, b23, acc2[1][1]);
            acc2[2][0] = fma2(d2, b01, acc2[2][0]); acc2[2][1] = fma2(d2, b23, acc2[2][1]);
            acc2[3][0] = fma2(d3, b01, acc2[3][0]); acc2[3][1] = fma2(d3, b23, acc2[3][1]);
        }
    }
    #pragma unroll
    for (int i = 0; i < 4; i++) {
        int e = e0 + tm * 4 + i;
        if (e < Te) {
            float c0, c1, c2, c3;
            unpack2(acc2[i][0], c0, c1);
            unpack2(acc2[i][1], c2, c3);
            size_t off = ((size_t)b * Te + e) * 64 + tn * 4;
            OUT[off + 0] = fabsf(c0 - EF[off + 0]);
            OUT[off + 1] = fabsf(c1 - EF[off + 1]);
            OUT[off + 2] = fabsf(c2 - EF[off + 2]);
            OUT[off + 3] = fabsf(c3 - EF[off + 3]);
        }
    }
}

// ---------------- final: attention pooling + MLP head + softmax ----------------
__global__ __launch_bounds__(256)
void final_kernel(const float* __restrict__ tt, const float* __restrict__ ef,
                  const float* __restrict__ aw, const float* __restrict__ ab,
                  const float* __restrict__ hw, const float* __restrict__ hb,
                  const float* __restrict__ cw, const float* __restrict__ cb,
                  float* __restrict__ out, int Te)
{
    const int b = blockIdx.x, tid = threadIdx.x;
    __shared__ float s_prob[2048];
    __shared__ float s_tmp[256];
    __shared__ float s_red[64];
    __shared__ float s_h[128];

    float loc[8];
    float lmax = -1e30f;
    #pragma unroll
    for (int ei = 0; ei < 8; ei++) {
        int e = ei * 256 + tid;
        float v = -1e30f;
        if (e < Te) {
            const float4* ep = (const float4*)&ef[((size_t)b * Te + e) * 64];
            float a = 0.f;
            #pragma unroll
            for (int q = 0; q < 16; q++) {
                float4 x = ep[q];
                a = fmaf(x.x, aw[4 * q + 0], a);
                a = fmaf(x.y, aw[4 * q + 1], a);
                a = fmaf(x.z, aw[4 * q + 2], a);
                a = fmaf(x.w, aw[4 * q + 3], a);
            }
            v = a + ab[0];
        }
        loc[ei] = v; lmax = fmaxf(lmax, v);
    }
    s_tmp[tid] = lmax; __syncthreads();
    for (int s = 128; s > 0; s >>= 1) { if (tid < s) s_tmp[tid] = fmaxf(s_tmp[tid], s_tmp[tid + s]); __syncthreads(); }
    float m = s_tmp[0]; __syncthreads();

    float lsum = 0.f;
    #pragma unroll
    for (int ei = 0; ei < 8; ei++) {
        int e = ei * 256 + tid;
        if (e < Te) { float ex = expf(loc[ei] - m); s_prob[e] = ex; lsum += ex; }
    }
    s_tmp[tid] = lsum; __syncthreads();
    for (int s = 128; s > 0; s >>= 1) { if (tid < s) s_tmp[tid] += s_tmp[tid + s]; __syncthreads(); }
    float inv = 1.f / s_tmp[0];
    __syncthreads();

    // red[d] = sum_e tt[b,e,d]*prob[e]
    const int d = tid & 63, part = tid >> 6;
    float acc = 0.f;
    for (int e = part; e < Te; e += 4)
        acc = fmaf(tt[((size_t)b * Te + e) * 64 + d], s_prob[e], acc);
    s_tmp[tid] = acc; __syncthreads();
    if (tid < 64)
        s_red[tid] = (s_tmp[tid] + s_tmp[tid + 64] + s_tmp[tid + 128] + s_tmp[tid + 192]) * inv;
    __syncthreads();

    if (tid < 128) {
        float a = hb[tid];
        #pragma unroll 8
        for (int k = 0; k < 64; k++) a = fmaf(s_red[k], hw[tid * 64 + k], a);
        s_h[tid] = fmaxf(a, 0.f);
    }
    __syncthreads();

    if (tid == 0) {
        float l0 = cb[0], l1 = cb[1];
        for (int j = 0; j < 128; j++) {
            l0 = fmaf(s_h[j], cw[j], l0);
            l1 = fmaf(s_h[j], cw[128 + j], l1);
        }
        float mm = fmaxf(l0, l1);
        float e0 = expf(l0 - mm), e1 = expf(l1 - mm);
        float s = e0 + e1;
        out[b * 2 + 0] = e0 / s;
        out[b * 2 + 1] = e1 / s;
    }
}

// ---------------- host driver ----------------
static void run_branch(const float* input, int Win0,
                       const float* w1, const float* b1,
                       const float* w2, const float* b2,
                       const float* w3, const float* b3,
                       const float* lw, const float* lb,
                       const float* wih, const float* whh,
                       const float* bih, const float* bhh,
                       float* gru_out,
                       float* pc1, float* pc2, float* pc3, float* ppool, float* plin)
{
    const int W1 = Win0 - 4, W2 = Win0 - 8, W3 = Win0 - 12, Wp = Win0 - 16;
    const int T = Wp;
    dim3 blk(16, 8);

    conv5x5_kernel<1><<<dim3((W1 + 63) / 64, (124 + 7) / 8, 4 * 2), blk>>>(
        input, w1, b1, pc1, 128, Win0, 124, W1, 16);
    conv5x5_kernel<16><<<dim3((W2 + 63) / 64, (120 + 7) / 8, 4 * 4), blk>>>(
        pc1, w2, b2, pc2, 124, W1, 120, W2, 32);
    conv5x5_kernel<32><<<dim3((W3 + 63) / 64, (116 + 7) / 8, 4 * 8), blk>>>(
        pc2, w3, b3, pc3, 120, W2, 116, W3, 64);

    int ptotal = 4 * 64 * 58 * Wp;
    maxpool_kernel<<<(ptotal + 255) / 256, 256>>>(pc3, ppool, W3, Wp, ptotal);

    gemm_nt64_kernel<<<(4 * T) / 64, 256>>>(ppool, lw, lb, plin, 4 * T, 3712);
    gru_kernel<<<T / 4, dim3(64, 4)>>>(plin, wih, whh, bih, bhh, gru_out, T);
}

extern "C" void kernel_launch(void* const* d_in, const int* in_sizes, int n_in,
                              void* d_out, int out_size)
{
    (void)in_sizes; (void)n_in; (void)out_size;

    const float* evaluation = (const float*)d_in[0];
    const float* templ      = (const float*)d_in[1];
    const float* e_w1 = (const float*)d_in[2];  const float* e_b1 = (const float*)d_in[3];
    const float* e_w2 = (const float*)d_in[4];  const float* e_b2 = (const float*)d_in[5];
    const float* e_w3 = (const float*)d_in[6];  const float* e_b3 = (const float*)d_in[7];
    const float* el_w = (const float*)d_in[8];  const float* el_b = (const float*)d_in[9];
    const float* eg_wih = (const float*)d_in[10]; const float* eg_whh = (const float*)d_in[11];
    const float* eg_bih = (const float*)d_in[12]; const float* eg_bhh = (const float*)d_in[13];
    const float* t_w1 = (const float*)d_in[14]; const float* t_b1 = (const float*)d_in[15];
    const float* t_w2 = (const float*)d_in[16]; const float* t_b2 = (const float*)d_in[17];
    const float* t_w3 = (const float*)d_in[18]; const float* t_b3 = (const float*)d_in[19];
    const float* tl_w = (const float*)d_in[20]; const float* tl_b = (const float*)d_in[21];
    const float* tg_wih = (const float*)d_in[22]; const float* tg_whh = (const float*)d_in[23];
    const float* tg_bih = (const float*)d_in[24]; const float* tg_bhh = (const float*)d_in[25];
    const float* a_w = (const float*)d_in[26]; const float* a_b = (const float*)d_in[27];
    const float* h_w = (const float*)d_in[28]; const float* h_b = (const float*)d_in[29];
    const float* c_w = (const float*)d_in[30]; const float* c_b = (const float*)d_in[31];

    float *pc1, *pc2, *pc3, *ppool, *plin, *pge, *pgt, *psc, *ptt;
    cudaGetSymbolAddress((void**)&pc1,  g_c1);
    cudaGetSymbolAddress((void**)&pc2,  g_c2);
    cudaGetSymbolAddress((void**)&pc3,  g_c3);
    cudaGetSymbolAddress((void**)&ppool, g_pool);
    cudaGetSymbolAddress((void**)&plin, g_lin);
    cudaGetSymbolAddress((void**)&pge,  g_gru_e);
    cudaGetSymbolAddress((void**)&pgt,  g_gru_t);
    cudaGetSymbolAddress((void**)&psc,  g_scores);
    cudaGetSymbolAddress((void**)&ptt,  g_tt);

    // Branches (sequential on default stream; buffers reused safely)
    run_branch(evaluation, 2048, e_w1, e_b1, e_w2, e_b2, e_w3, e_b3,
               el_w, el_b, eg_wih, eg_whh, eg_bih, eg_bhh, pge,
               pc1, pc2, pc3, ppool, plin);
    run_branch(templ, 1040, t_w1, t_b1, t_w2, t_b2, t_w3, t_b3,
               tl_w, tl_b, tg_wih, tg_whh, tg_bih, tg_bhh, pgt,
               pc1, pc2, pc3, ppool, plin);

    const int Tt = 1024, Te = 2032;
    scores_softmax_kernel<<<dim3(Tt, 4), 256>>>(pgt, pge, psc, Tt, Te);
    gemm_tt_kernel<<<dim3((Te + 63) / 64, 4), 256>>>(psc, pgt, pge, ptt, Tt, Te);
    final_kernel<<<4, 256>>>(ptt, pge, a_w, a_b, h_w, h_b, c_w, c_b,
                             (float*)d_out, Te);
}